// round 4
// baseline (speedup 1.0000x reference)
#include <cuda_runtime.h>
#include <cstdint>

#define FULL 0xffffffffu

static constexpr int Tn = 1024;
static constexpr int Kn = 48;
static constexpr int Bn = 512;

__device__ __forceinline__ unsigned long long pack2(float lo, float hi) {
    unsigned long long r;
    asm("mov.b64 %0, {%1, %2};" : "=l"(r) : "f"(lo), "f"(hi));
    return r;
}
__device__ __forceinline__ void unpack2(unsigned long long v, float& lo, float& hi) {
    asm("mov.b64 {%0, %1}, %2;" : "=f"(lo), "=f"(hi) : "l"(v));
}
__device__ __forceinline__ unsigned long long fma2(unsigned long long a, unsigned long long b,
                                                   unsigned long long c) {
    unsigned long long d;
    asm("fma.rn.f32x2 %0, %1, %2, %3;" : "=l"(d) : "l"(a), "l"(b), "l"(c));
    return d;
}
__device__ __forceinline__ unsigned long long add2(unsigned long long a, unsigned long long b) {
    unsigned long long d;
    asm("add.rn.f32x2 %0, %1, %2;" : "=l"(d) : "l"(a), "l"(b));
    return d;
}
__device__ __forceinline__ float rcp_approx(float x) {
    float r;
    asm("rcp.approx.f32 %0, %1;" : "=f"(r) : "f"(x));
    return r;
}

__global__ void _CRF_zero_kernel(float* out) {
    if (threadIdx.x == 0) out[0] = 0.0f;
}

__global__ void __launch_bounds__(128) _CRF_15530601742419_kernel(
    const float* __restrict__ E,            // (B, T, K) emissions
    const int* __restrict__ tags,           // (B, T)
    const void* __restrict__ mask,          // (B, T) bool — layout detected at runtime
    const float* __restrict__ Tr,           // (K, K) transitions
    const float* __restrict__ Sv,           // (K,) start
    const float* __restrict__ Ev,           // (K,) end
    float* __restrict__ out)
{
    __shared__ __align__(16) float sp[4][2][Kn];

    const int warp = threadIdx.x >> 5;
    const int lane = threadIdx.x & 31;
    const int b = blockIdx.x * 4 + warp;
    const bool vhi = (lane < 16);
    const float* __restrict__ Eb = E + (size_t)b * Tn * Kn;

    // ---- sequence length from mask (runtime layout detection) ----
    int len;
    {
        const unsigned char* mb = (const unsigned char*)mask;
        int si;
        if (mb[1] != 0) {
            // 1-byte bool layout
            const unsigned* mw = (const unsigned*)(mb + (size_t)b * Tn) + lane * 8;
            unsigned s = 0;
            #pragma unroll
            for (int i = 0; i < 8; i++) s = __dp4a(mw[i], 0x01010101u, s);
            si = (int)s;
        } else {
            // 4-byte layout (int32/float32): count nonzero words
            const uint4* mw = (const uint4*)((const unsigned*)mask + (size_t)b * Tn) + lane * 8;
            int s = 0;
            #pragma unroll
            for (int i = 0; i < 8; i++) {
                uint4 q = mw[i];
                s += (q.x != 0) + (q.y != 0) + (q.z != 0) + (q.w != 0);
            }
            si = s;
        }
        #pragma unroll
        for (int o = 16; o; o >>= 1) si += __shfl_xor_sync(FULL, si, o);
        len = si;
    }

    // ---- sequence score (gold path) ----
    float seq = 0.0f;
    {
        const int* __restrict__ tg = tags + (size_t)b * Tn;
        float s = 0.0f;
        #pragma unroll 4
        for (int t = lane; t < Tn; t += 32) {
            int tag = tg[t];
            float em = Eb[t * Kn + tag];
            if (t == 0)        s += Sv[tag] + em;
            else if (t < len)  s += Tr[tg[t - 1] * Kn + tag] + em;
        }
        #pragma unroll
        for (int o = 16; o; o >>= 1) s += __shfl_xor_sync(FULL, s, o);
        if (lane == 0) s += Ev[tg[len - 1]];
        seq = s; // complete on lane 0
    }

    // ---- exp(transitions) column pairs into registers ----
    // Lane owns output states j=lane (lo) and j=lane+32 (hi, valid if lane<16).
    unsigned long long Mlo[24], Mhi[24];
    #pragma unroll
    for (int k = 0; k < 24; k++) {
        float a0 = __expf(Tr[(2 * k) * Kn + lane]);
        float a1 = __expf(Tr[(2 * k + 1) * Kn + lane]);
        Mlo[k] = pack2(a0, a1);
        float b0 = 0.0f, b1 = 0.0f;
        if (vhi) {
            b0 = __expf(Tr[(2 * k) * Kn + lane + 32]);
            b1 = __expf(Tr[(2 * k + 1) * Kn + lane + 32]);
        }
        Mhi[k] = pack2(b0, b1);
    }

    // ---- init: p = exp(score0 - score0[0]),  C = score0[0] ----
    float s_lo = Sv[lane] + Eb[lane];
    float s_hi = vhi ? (Sv[lane + 32] + Eb[lane + 32]) : -1e30f;
    const float s0 = __shfl_sync(FULL, s_lo, 0);
    float p_lo = __expf(s_lo - s0);
    float p_hi = vhi ? __expf(s_hi - s0) : 0.0f;
    double C = (double)s0;

    // ---- emission prefetch pipeline (exp'd, distance 4 steps) ----
    float pf_lo[4], pf_hi[4];
    #pragma unroll
    for (int u = 0; u < 4; u++) {
        int t = 1 + u;
        pf_lo[u] = __expf(Eb[t * Kn + lane]);
        pf_hi[u] = vhi ? __expf(Eb[t * Kn + lane + 32]) : 0.0f;
    }

    float* const spw0 = sp[warp][0];
    float* const spw1 = sp[warp][1];

    // ---- forward recursion t = 1 .. 1023 (exp domain, renorm by p[0] each step) ----
    #pragma unroll 1
    for (int g = 0; g < 256; g++) {
        #pragma unroll
        for (int u = 0; u < 4; u++) {
            const int t = 1 + g * 4 + u;
            const float eem_lo = pf_lo[u];
            const float eem_hi = pf_hi[u];
            int tp = t + 4; if (tp > Tn - 1) tp = Tn - 1;
            pf_lo[u] = __expf(Eb[tp * Kn + lane]);
            pf_hi[u] = vhi ? __expf(Eb[tp * Kn + lane + 32]) : 0.0f;

            if (t < Tn) {
                float* const buf = (t & 1) ? spw1 : spw0;
                buf[lane] = p_lo;
                if (vhi) buf[lane + 32] = p_hi;
                __syncwarp();

                const ulonglong2* __restrict__ pb = (const ulonglong2*)buf;
                unsigned long long a0 = 0ull, a1 = 0ull, a2 = 0ull, a3 = 0ull;
                unsigned long long b0 = 0ull, b1 = 0ull, b2 = 0ull, b3 = 0ull;
                float p00 = 0.0f, junk;
                #pragma unroll
                for (int k = 0; k < 12; k++) {
                    ulonglong2 q = pb[k];   // (p[4k],p[4k+1]) , (p[4k+2],p[4k+3])
                    if (k == 0) unpack2(q.x, p00, junk);
                    if (k & 1) {
                        a1 = fma2(q.x, Mlo[2 * k],     a1);
                        a3 = fma2(q.y, Mlo[2 * k + 1], a3);
                        b1 = fma2(q.x, Mhi[2 * k],     b1);
                        b3 = fma2(q.y, Mhi[2 * k + 1], b3);
                    } else {
                        a0 = fma2(q.x, Mlo[2 * k],     a0);
                        a2 = fma2(q.y, Mlo[2 * k + 1], a2);
                        b0 = fma2(q.x, Mhi[2 * k],     b0);
                        b2 = fma2(q.y, Mhi[2 * k + 1], b2);
                    }
                }
                // renorm factor (off-chain MUFU, overlaps fma chain)
                const float r = rcp_approx(p00);
                const float lp0 = __logf(p00);

                float x0, x1, y0, y1;
                unpack2(add2(add2(a0, a1), add2(a2, a3)), x0, x1);
                unpack2(add2(add2(b0, b1), add2(b2, b3)), y0, y1);

                const float pn_lo = (x0 + x1) * eem_lo * r;
                const float pn_hi = (y0 + y1) * eem_hi * r;

                if (t < len) {            // uniform across warp
                    p_lo = pn_lo;
                    p_hi = vhi ? pn_hi : 0.0f;
                    C += (double)lp0;
                }
            }
        }
    }

    // ---- log_z = C + log( sum_i p_i * exp(End_i) ) ----
    {
        float v = p_lo * __expf(Ev[lane]);
        if (vhi) v += p_hi * __expf(Ev[lane + 32]);
        #pragma unroll
        for (int o = 16; o; o >>= 1) v += __shfl_xor_sync(FULL, v, o);
        if (lane == 0) {
            const float log_z = (float)(C + (double)__logf(v));
            atomicAdd(out, (log_z - seq) * (1.0f / (float)Bn));
        }
    }
}

extern "C" void kernel_launch(void* const* d_in, const int* in_sizes, int n_in,
                              void* d_out, int out_size) {
    const float* E    = (const float*)d_in[0];
    const int*   tags = (const int*)d_in[1];
    const void*  mask = (const void*)d_in[2];
    const float* Tr   = (const float*)d_in[3];
    const float* Sv   = (const float*)d_in[4];
    const float* Ev   = (const float*)d_in[5];
    float* out = (float*)d_out;

    _CRF_zero_kernel<<<1, 32>>>(out);
    _CRF_15530601742419_kernel<<<Bn / 4, 128>>>(E, tags, mask, Tr, Sv, Ev, out);
}

// round 6
// speedup vs baseline: 1.3901x; 1.3901x over previous
#include <cuda_runtime.h>
#include <cstdint>

#define FULL 0xffffffffu

static constexpr int Tn = 1024;
static constexpr int Kn = 48;
static constexpr int Bn = 512;

__device__ __forceinline__ unsigned long long pack2(float lo, float hi) {
    unsigned long long r;
    asm("mov.b64 %0, {%1, %2};" : "=l"(r) : "f"(lo), "f"(hi));
    return r;
}
__device__ __forceinline__ void unpack2(unsigned long long v, float& lo, float& hi) {
    asm("mov.b64 {%0, %1}, %2;" : "=f"(lo), "=f"(hi) : "l"(v));
}
__device__ __forceinline__ unsigned long long fma2(unsigned long long a, unsigned long long b,
                                                   unsigned long long c) {
    unsigned long long d;
    asm("fma.rn.f32x2 %0, %1, %2, %3;" : "=l"(d) : "l"(a), "l"(b), "l"(c));
    return d;
}
__device__ __forceinline__ unsigned long long add2(unsigned long long a, unsigned long long b) {
    unsigned long long d;
    asm("add.rn.f32x2 %0, %1, %2;" : "=l"(d) : "l"(a), "l"(b));
    return d;
}
__device__ __forceinline__ float rcp_approx(float x) {
    float r;
    asm("rcp.approx.f32 %0, %1;" : "=f"(r) : "f"(x));
    return r;
}

__global__ void _CRF_zero_kernel(float* out) {
    if (threadIdx.x == 0) out[0] = 0.0f;
}

__global__ void __launch_bounds__(128) _CRF_15530601742419_kernel(
    const float* __restrict__ E,            // (B, T, K) emissions
    const int* __restrict__ tags,           // (B, T)
    const void* __restrict__ mask,          // (B, T) bool — layout detected at runtime
    const float* __restrict__ Tr,           // (K, K) transitions
    const float* __restrict__ Sv,           // (K,) start
    const float* __restrict__ Ev,           // (K,) end
    float* __restrict__ out)
{
    __shared__ __align__(16) float sp[4][2][Kn];

    const int warp = threadIdx.x >> 5;
    const int lane = threadIdx.x & 31;
    const int b = blockIdx.x * 4 + warp;
    const bool vhi = (lane < 16);
    const float* __restrict__ Eb = E + (size_t)b * Tn * Kn;

    // ---- sequence length from mask (runtime layout detection) ----
    int len;
    {
        const unsigned char* mb = (const unsigned char*)mask;
        int si;
        if (mb[1] != 0) {
            // 1-byte bool layout
            const unsigned* mw = (const unsigned*)(mb + (size_t)b * Tn) + lane * 8;
            unsigned s = 0;
            #pragma unroll
            for (int i = 0; i < 8; i++) s = __dp4a(mw[i], 0x01010101u, s);
            si = (int)s;
        } else {
            // 4-byte layout (int32/float32): count nonzero words
            const uint4* mw = (const uint4*)((const unsigned*)mask + (size_t)b * Tn) + lane * 8;
            int s = 0;
            #pragma unroll
            for (int i = 0; i < 8; i++) {
                uint4 q = mw[i];
                s += (q.x != 0) + (q.y != 0) + (q.z != 0) + (q.w != 0);
            }
            si = s;
        }
        #pragma unroll
        for (int o = 16; o; o >>= 1) si += __shfl_xor_sync(FULL, si, o);
        len = si;
    }

    // ---- sequence score (gold path) ----
    float seq = 0.0f;
    {
        const int* __restrict__ tg = tags + (size_t)b * Tn;
        float s = 0.0f;
        #pragma unroll 4
        for (int t = lane; t < Tn; t += 32) {
            int tag = tg[t];
            float em = Eb[t * Kn + tag];
            if (t == 0)        s += Sv[tag] + em;
            else if (t < len)  s += Tr[tg[t - 1] * Kn + tag] + em;
        }
        #pragma unroll
        for (int o = 16; o; o >>= 1) s += __shfl_xor_sync(FULL, s, o);
        if (lane == 0) s += Ev[tg[len - 1]];
        seq = s; // complete on lane 0
    }

    // ---- exp(transitions) column pairs into registers ----
    // Lane owns output states j=lane (lo) and j=lane+32 (hi, valid if lane<16).
    unsigned long long Mlo[24], Mhi[24];
    #pragma unroll
    for (int k = 0; k < 24; k++) {
        float a0 = __expf(Tr[(2 * k) * Kn + lane]);
        float a1 = __expf(Tr[(2 * k + 1) * Kn + lane]);
        Mlo[k] = pack2(a0, a1);
        float b0 = 0.0f, b1 = 0.0f;
        if (vhi) {
            b0 = __expf(Tr[(2 * k) * Kn + lane + 32]);
            b1 = __expf(Tr[(2 * k + 1) * Kn + lane + 32]);
        }
        Mhi[k] = pack2(b0, b1);
    }

    // ---- init: p = exp(score0 - score0[0]),  C = score0[0] (Kahan fp32) ----
    float s_lo = Sv[lane] + Eb[lane];
    float s_hi = vhi ? (Sv[lane + 32] + Eb[lane + 32]) : -1e30f;
    const float s0 = __shfl_sync(FULL, s_lo, 0);
    float p_lo = __expf(s_lo - s0);
    float p_hi = vhi ? __expf(s_hi - s0) : 0.0f;
    float Csum = s0, Ccomp = 0.0f;

    // ---- emission prefetch pipeline (RAW values, distance 4 steps) ----
    float pf_lo[4], pf_hi[4];
    #pragma unroll
    for (int u = 0; u < 4; u++) {
        int t = 1 + u;
        pf_lo[u] = Eb[t * Kn + lane];
        pf_hi[u] = vhi ? Eb[t * Kn + lane + 32] : 0.0f;
    }

    float* const spw0 = sp[warp][0];
    float* const spw1 = sp[warp][1];

    // ---- forward recursion t = 1 .. 1023 (exp domain, renorm by p[0] each step) ----
    #pragma unroll 1
    for (int g = 0; g < 256; g++) {
        #pragma unroll
        for (int u = 0; u < 4; u++) {
            const int t = 1 + g * 4 + u;
            // exp of current emission: register-only dependency, issues early,
            // MUFU latency overlaps the STS/sync/LDS/fma chain below.
            const float eem_lo = __expf(pf_lo[u]);
            const float eem_hi = __expf(pf_hi[u]);
            // refill prefetch (raw load, consumed 4 steps later)
            int tp = t + 4; if (tp > Tn - 1) tp = Tn - 1;
            pf_lo[u] = Eb[tp * Kn + lane];
            pf_hi[u] = vhi ? Eb[tp * Kn + lane + 32] : 0.0f;

            if (t < Tn) {
                float* const buf = (t & 1) ? spw1 : spw0;
                buf[lane] = p_lo;
                if (vhi) buf[lane + 32] = p_hi;
                __syncwarp();

                const ulonglong2* __restrict__ pb = (const ulonglong2*)buf;
                unsigned long long a0 = 0ull, a1 = 0ull, a2 = 0ull, a3 = 0ull;
                unsigned long long b0 = 0ull, b1 = 0ull, b2 = 0ull, b3 = 0ull;
                float p00 = 0.0f, junk;
                #pragma unroll
                for (int k = 0; k < 12; k++) {
                    ulonglong2 q = pb[k];   // (p[4k],p[4k+1]) , (p[4k+2],p[4k+3])
                    if (k == 0) unpack2(q.x, p00, junk);
                    if (k & 1) {
                        a1 = fma2(q.x, Mlo[2 * k],     a1);
                        a3 = fma2(q.y, Mlo[2 * k + 1], a3);
                        b1 = fma2(q.x, Mhi[2 * k],     b1);
                        b3 = fma2(q.y, Mhi[2 * k + 1], b3);
                    } else {
                        a0 = fma2(q.x, Mlo[2 * k],     a0);
                        a2 = fma2(q.y, Mlo[2 * k + 1], a2);
                        b0 = fma2(q.x, Mhi[2 * k],     b0);
                        b2 = fma2(q.y, Mhi[2 * k + 1], b2);
                    }
                }
                // renorm + emission factors (off critical path: overlap fma tree)
                const float r = rcp_approx(p00);
                const float lp0 = __logf(p00);
                const float er_lo = eem_lo * r;
                const float er_hi = eem_hi * r;

                float x0, x1, y0, y1;
                unpack2(add2(add2(a0, a1), add2(a2, a3)), x0, x1);
                unpack2(add2(add2(b0, b1), add2(b2, b3)), y0, y1);

                const float pn_lo = (x0 + x1) * er_lo;
                const float pn_hi = (y0 + y1) * er_hi;

                const bool upd = (t < len);     // uniform across warp
                p_lo = upd ? pn_lo : p_lo;
                p_hi = upd ? (vhi ? pn_hi : 0.0f) : p_hi;
                // Kahan-compensated accumulation of log-offset (off-chain)
                const float add = upd ? lp0 : 0.0f;
                const float y   = add - Ccomp;
                const float tt  = Csum + y;
                Ccomp = (tt - Csum) - y;
                Csum  = tt;
            }
        }
    }

    // ---- log_z = C + log( sum_i p_i * exp(End_i) ) ----
    {
        float v = p_lo * __expf(Ev[lane]);
        if (vhi) v += p_hi * __expf(Ev[lane + 32]);
        #pragma unroll
        for (int o = 16; o; o >>= 1) v += __shfl_xor_sync(FULL, v, o);
        if (lane == 0) {
            const float log_z = (Csum - Ccomp) + __logf(v);
            atomicAdd(out, (log_z - seq) * (1.0f / (float)Bn));
        }
    }
}

extern "C" void kernel_launch(void* const* d_in, const int* in_sizes, int n_in,
                              void* d_out, int out_size) {
    const float* E    = (const float*)d_in[0];
    const int*   tags = (const int*)d_in[1];
    const void*  mask = (const void*)d_in[2];
    const float* Tr   = (const float*)d_in[3];
    const float* Sv   = (const float*)d_in[4];
    const float* Ev   = (const float*)d_in[5];
    float* out = (float*)d_out;

    _CRF_zero_kernel<<<1, 32>>>(out);
    _CRF_15530601742419_kernel<<<Bn / 4, 128>>>(E, tags, mask, Tr, Sv, Ev, out);
}

// round 7
// speedup vs baseline: 1.5394x; 1.1074x over previous
#include <cuda_runtime.h>
#include <cstdint>

#define FULL 0xffffffffu

static constexpr int Tn = 1024;
static constexpr int Kn = 48;
static constexpr int Bn = 512;

__device__ __forceinline__ unsigned long long pack2(float lo, float hi) {
    unsigned long long r;
    asm("mov.b64 %0, {%1, %2};" : "=l"(r) : "f"(lo), "f"(hi));
    return r;
}
__device__ __forceinline__ void unpack2(unsigned long long v, float& lo, float& hi) {
    asm("mov.b64 {%0, %1}, %2;" : "=f"(lo), "=f"(hi) : "l"(v));
}
__device__ __forceinline__ unsigned long long fma2(unsigned long long a, unsigned long long b,
                                                   unsigned long long c) {
    unsigned long long d;
    asm("fma.rn.f32x2 %0, %1, %2, %3;" : "=l"(d) : "l"(a), "l"(b), "l"(c));
    return d;
}
__device__ __forceinline__ unsigned long long add2(unsigned long long a, unsigned long long b) {
    unsigned long long d;
    asm("add.rn.f32x2 %0, %1, %2;" : "=l"(d) : "l"(a), "l"(b));
    return d;
}
__device__ __forceinline__ float rcp_approx(float x) {
    float r;
    asm("rcp.approx.f32 %0, %1;" : "=f"(r) : "f"(x));
    return r;
}

__global__ void _CRF_zero_kernel(float* out) {
    if (threadIdx.x == 0) out[0] = 0.0f;
}

__global__ void __launch_bounds__(128) _CRF_15530601742419_kernel(
    const float* __restrict__ E,            // (B, T, K) emissions
    const int* __restrict__ tags,           // (B, T)
    const void* __restrict__ mask,          // (B, T) bool — layout detected at runtime
    const float* __restrict__ Tr,           // (K, K) transitions
    const float* __restrict__ Sv,           // (K,) start
    const float* __restrict__ Ev,           // (K,) end
    float* __restrict__ out)
{
    __shared__ __align__(16) float sp[4][Kn];

    const int warp = threadIdx.x >> 5;
    const int lane = threadIdx.x & 31;
    const int b = blockIdx.x * 4 + warp;
    const bool vhi = (lane < 16);
    const float* __restrict__ Eb = E + (size_t)b * Tn * Kn;

    // ---- sequence length from mask (runtime layout detection) ----
    int len;
    {
        const unsigned char* mb = (const unsigned char*)mask;
        int si;
        if (mb[1] != 0) {
            const unsigned* mw = (const unsigned*)(mb + (size_t)b * Tn) + lane * 8;
            unsigned s = 0;
            #pragma unroll
            for (int i = 0; i < 8; i++) s = __dp4a(mw[i], 0x01010101u, s);
            si = (int)s;
        } else {
            const uint4* mw = (const uint4*)((const unsigned*)mask + (size_t)b * Tn) + lane * 8;
            int s = 0;
            #pragma unroll
            for (int i = 0; i < 8; i++) {
                uint4 q = mw[i];
                s += (q.x != 0) + (q.y != 0) + (q.z != 0) + (q.w != 0);
            }
            si = s;
        }
        #pragma unroll
        for (int o = 16; o; o >>= 1) si += __shfl_xor_sync(FULL, si, o);
        len = si;
    }

    // ---- sequence score (gold path) ----
    float seq = 0.0f;
    {
        const int* __restrict__ tg = tags + (size_t)b * Tn;
        float s = 0.0f;
        #pragma unroll 4
        for (int t = lane; t < Tn; t += 32) {
            int tag = tg[t];
            float em = Eb[t * Kn + tag];
            if (t == 0)        s += Sv[tag] + em;
            else if (t < len)  s += Tr[tg[t - 1] * Kn + tag] + em;
        }
        #pragma unroll
        for (int o = 16; o; o >>= 1) s += __shfl_xor_sync(FULL, s, o);
        if (lane == 0) s += Ev[tg[len - 1]];
        seq = s; // complete on lane 0
    }

    // ---- exp(transitions) column pairs into registers ----
    unsigned long long Mlo[24], Mhi[24];
    #pragma unroll
    for (int k = 0; k < 24; k++) {
        float a0 = __expf(Tr[(2 * k) * Kn + lane]);
        float a1 = __expf(Tr[(2 * k + 1) * Kn + lane]);
        Mlo[k] = pack2(a0, a1);
        float b0 = 0.0f, b1 = 0.0f;
        if (vhi) {
            b0 = __expf(Tr[(2 * k) * Kn + lane + 32]);
            b1 = __expf(Tr[(2 * k + 1) * Kn + lane + 32]);
        }
        Mhi[k] = pack2(b0, b1);
    }

    // ---- init: p = exp(score0 - score0[0]),  C = score0[0] (Kahan fp32) ----
    float s_lo = Sv[lane] + Eb[lane];
    float s_hi = vhi ? (Sv[lane + 32] + Eb[lane + 32]) : -1e30f;
    const float s0 = __shfl_sync(FULL, s_lo, 0);
    float p_lo = __expf(s_lo - s0);
    float p_hi = vhi ? __expf(s_hi - s0) : 0.0f;
    float Csum = s0, Ccomp = 0.0f;

    // ---- emission prefetch pipeline (raw values, distance 4 steps) ----
    float pf_lo[4], pf_hi[4];
    #pragma unroll
    for (int u = 0; u < 4; u++) {
        int t = 1 + u;
        pf_lo[u] = Eb[t * Kn + lane];
        pf_hi[u] = vhi ? Eb[t * Kn + lane + 32] : 0.0f;
    }

    float* const buf = sp[warp];

    // ---- forward recursion t = 1 .. len-1 (exp domain, renorm by p[0]) ----
    #pragma unroll 1
    for (int t0 = 1; t0 < len; t0 += 4) {
        #pragma unroll
        for (int u = 0; u < 4; u++) {
            const int t = t0 + u;
            if (t < len) {                    // uniform across warp
                // ---- exchange first: start the serial chain immediately ----
                buf[lane] = p_lo;
                if (vhi) buf[lane + 32] = p_hi;
                __syncwarp();

                // off-chain work scheduled into the sync/LDS shadow:
                const float eem_lo = __expf(pf_lo[u]);
                const float eem_hi = __expf(pf_hi[u]);
                int tp = t + 4; if (tp > Tn - 1) tp = Tn - 1;
                pf_lo[u] = Eb[tp * Kn + lane];
                pf_hi[u] = vhi ? Eb[tp * Kn + lane + 32] : 0.0f;

                // scalar broadcast load of p[0] (decoupled from fma operands)
                const float p00 = buf[0];
                const float r   = rcp_approx(p00);
                const float lp0 = __logf(p00);
                const float er_lo = eem_lo * r;
                const float er_hi = eem_hi * r;

                // 48 x fma2, 4 accumulators, sequential k (R2 structure)
                const ulonglong2* __restrict__ pb = (const ulonglong2*)buf;
                unsigned long long a0 = 0ull, a1 = 0ull;
                unsigned long long b0 = 0ull, b1 = 0ull;
                #pragma unroll
                for (int k = 0; k < 12; k++) {
                    ulonglong2 q = pb[k];   // (p[4k],p[4k+1]) , (p[4k+2],p[4k+3])
                    a0 = fma2(q.x, Mlo[2 * k],     a0);
                    a1 = fma2(q.y, Mlo[2 * k + 1], a1);
                    b0 = fma2(q.x, Mhi[2 * k],     b0);
                    b1 = fma2(q.y, Mhi[2 * k + 1], b1);
                }
                float x0, x1, y0, y1;
                unpack2(add2(a0, a1), x0, x1);
                unpack2(add2(b0, b1), y0, y1);

                p_lo = (x0 + x1) * er_lo;
                p_hi = vhi ? (y0 + y1) * er_hi : 0.0f;

                // Kahan accumulation of the log-offset (off-chain)
                const float y  = lp0 - Ccomp;
                const float tt = Csum + y;
                Ccomp = (tt - Csum) - y;
                Csum  = tt;
            }
        }
    }

    // ---- log_z = C + log( sum_i p_i * exp(End_i) ) ----
    {
        float v = p_lo * __expf(Ev[lane]);
        if (vhi) v += p_hi * __expf(Ev[lane + 32]);
        #pragma unroll
        for (int o = 16; o; o >>= 1) v += __shfl_xor_sync(FULL, v, o);
        if (lane == 0) {
            const float log_z = (Csum - Ccomp) + __logf(v);
            atomicAdd(out, (log_z - seq) * (1.0f / (float)Bn));
        }
    }
}

extern "C" void kernel_launch(void* const* d_in, const int* in_sizes, int n_in,
                              void* d_out, int out_size) {
    const float* E    = (const float*)d_in[0];
    const int*   tags = (const int*)d_in[1];
    const void*  mask = (const void*)d_in[2];
    const float* Tr   = (const float*)d_in[3];
    const float* Sv   = (const float*)d_in[4];
    const float* Ev   = (const float*)d_in[5];
    float* out = (float*)d_out;

    _CRF_zero_kernel<<<1, 32>>>(out);
    _CRF_15530601742419_kernel<<<Bn / 4, 128>>>(E, tags, mask, Tr, Sv, Ev, out);
}

// round 8
// speedup vs baseline: 2.6363x; 1.7126x over previous
#include <cuda_runtime.h>
#include <cstdint>

#define FULL 0xffffffffu

static constexpr int Tn = 1024;
static constexpr int Kn = 48;
static constexpr int Bn = 512;

__device__ __forceinline__ unsigned long long pack2(float lo, float hi) {
    unsigned long long r;
    asm("mov.b64 %0, {%1, %2};" : "=l"(r) : "f"(lo), "f"(hi));
    return r;
}
__device__ __forceinline__ void unpack2(unsigned long long v, float& lo, float& hi) {
    asm("mov.b64 {%0, %1}, %2;" : "=f"(lo), "=f"(hi) : "l"(v));
}
__device__ __forceinline__ unsigned long long fma2(unsigned long long a, unsigned long long b,
                                                   unsigned long long c) {
    unsigned long long d;
    asm("fma.rn.f32x2 %0, %1, %2, %3;" : "=l"(d) : "l"(a), "l"(b), "l"(c));
    return d;
}
__device__ __forceinline__ unsigned long long add2(unsigned long long a, unsigned long long b) {
    unsigned long long d;
    asm("add.rn.f32x2 %0, %1, %2;" : "=l"(d) : "l"(a), "l"(b));
    return d;
}
__device__ __forceinline__ float rcp_approx(float x) {
    float r;
    asm("rcp.approx.f32 %0, %1;" : "=f"(r) : "f"(x));
    return r;
}

__global__ void _CRF_zero_kernel(float* out) {
    if (threadIdx.x == 0) out[0] = 0.0f;
}

__global__ void __launch_bounds__(128) _CRF_15530601742419_kernel(
    const float* __restrict__ E,            // (B, T, K) emissions
    const int* __restrict__ tags,           // (B, T)
    const void* __restrict__ mask,          // (B, T) bool — layout detected at runtime
    const float* __restrict__ Tr,           // (K, K) transitions
    const float* __restrict__ Sv,           // (K,) start
    const float* __restrict__ Ev,           // (K,) end
    float* __restrict__ out)
{
    __shared__ __align__(16) float sp[4][Kn];

    const int warp = threadIdx.x >> 5;
    const int lane = threadIdx.x & 31;
    const int b = blockIdx.x * 4 + warp;
    const bool vhi = (lane < 16);
    const float* __restrict__ Eb = E + (size_t)b * Tn * Kn;

    // ---- sequence length from mask (runtime layout detection) ----
    int len;
    {
        const unsigned char* mb = (const unsigned char*)mask;
        int si;
        if (mb[1] != 0) {
            const unsigned* mw = (const unsigned*)(mb + (size_t)b * Tn) + lane * 8;
            unsigned s = 0;
            #pragma unroll
            for (int i = 0; i < 8; i++) s = __dp4a(mw[i], 0x01010101u, s);
            si = (int)s;
        } else {
            const uint4* mw = (const uint4*)((const unsigned*)mask + (size_t)b * Tn) + lane * 8;
            int s = 0;
            #pragma unroll
            for (int i = 0; i < 8; i++) {
                uint4 q = mw[i];
                s += (q.x != 0) + (q.y != 0) + (q.z != 0) + (q.w != 0);
            }
            si = s;
        }
        #pragma unroll
        for (int o = 16; o; o >>= 1) si += __shfl_xor_sync(FULL, si, o);
        len = si;
    }

    // ---- sequence score (gold path) ----
    float seq = 0.0f;
    {
        const int* __restrict__ tg = tags + (size_t)b * Tn;
        float s = 0.0f;
        #pragma unroll 4
        for (int t = lane; t < Tn; t += 32) {
            int tag = tg[t];
            float em = Eb[t * Kn + tag];
            if (t == 0)        s += Sv[tag] + em;
            else if (t < len)  s += Tr[tg[t - 1] * Kn + tag] + em;
        }
        #pragma unroll
        for (int o = 16; o; o >>= 1) s += __shfl_xor_sync(FULL, s, o);
        if (lane == 0) s += Ev[tg[len - 1]];
        seq = s; // complete on lane 0
    }

    // ---- exp(transitions) column pairs into registers ----
    // Lane owns output states j=lane (lo) and j=lane+32 (hi, valid if lane<16).
    unsigned long long Mlo[24], Mhi[24];
    #pragma unroll
    for (int k = 0; k < 24; k++) {
        float a0 = __expf(Tr[(2 * k) * Kn + lane]);
        float a1 = __expf(Tr[(2 * k + 1) * Kn + lane]);
        Mlo[k] = pack2(a0, a1);
        float b0 = 0.0f, b1 = 0.0f;
        if (vhi) {
            b0 = __expf(Tr[(2 * k) * Kn + lane + 32]);
            b1 = __expf(Tr[(2 * k + 1) * Kn + lane + 32]);
        }
        Mhi[k] = pack2(b0, b1);
    }

    // ---- init: p = exp(score0 - score0[0]),  C = score0[0] (Kahan fp32) ----
    float s_lo = Sv[lane] + Eb[lane];
    float s_hi = vhi ? (Sv[lane + 32] + Eb[lane + 32]) : -1e30f;
    const float s0 = __shfl_sync(FULL, s_lo, 0);
    float p_lo = __expf(s_lo - s0);
    float p_hi = vhi ? __expf(s_hi - s0) : 0.0f;
    float Csum = s0, Ccomp = 0.0f;

    // ---- emission prefetch pipeline (raw values, distance 4 steps) ----
    float pf_lo[4], pf_hi[4];
    #pragma unroll
    for (int u = 0; u < 4; u++) {
        int t = 1 + u;
        pf_lo[u] = Eb[t * Kn + lane];
        pf_hi[u] = vhi ? Eb[t * Kn + lane + 32] : 0.0f;
    }

    float* const buf = sp[warp];

    // ---- forward recursion: fixed 1024 steps (t = 1..1024), branch-free body.
    // t >= len (including the always-dead t == 1024) is discarded by selects,
    // so there is NO runtime-bounded control flow inside the loop.
    #pragma unroll 1
    for (int g = 0; g < 256; g++) {
        #pragma unroll
        for (int u = 0; u < 4; u++) {
            const int t = 1 + g * 4 + u;

            // ---- exchange first: start the serial chain immediately ----
            buf[lane] = p_lo;
            if (vhi) buf[lane + 32] = p_hi;
            __syncwarp();

            // off-chain work scheduled into the sync/LDS shadow:
            const float eem_lo = __expf(pf_lo[u]);
            const float eem_hi = __expf(pf_hi[u]);
            int tp = t + 4; if (tp > Tn - 1) tp = Tn - 1;
            pf_lo[u] = Eb[tp * Kn + lane];
            pf_hi[u] = vhi ? Eb[tp * Kn + lane + 32] : 0.0f;

            // scalar broadcast of p[0]; renorm factors (off critical path)
            const float p00 = buf[0];
            const float r   = rcp_approx(p00);
            const float lp0 = __logf(p00);
            const float er_lo = eem_lo * r;
            const float er_hi = eem_hi * r;

            // 48 x fma2, 4 accumulators, sequential k
            const ulonglong2* __restrict__ pb = (const ulonglong2*)buf;
            unsigned long long a0 = 0ull, a1 = 0ull;
            unsigned long long b0 = 0ull, b1 = 0ull;
            #pragma unroll
            for (int k = 0; k < 12; k++) {
                ulonglong2 q = pb[k];   // (p[4k],p[4k+1]) , (p[4k+2],p[4k+3])
                a0 = fma2(q.x, Mlo[2 * k],     a0);
                a1 = fma2(q.y, Mlo[2 * k + 1], a1);
                b0 = fma2(q.x, Mhi[2 * k],     b0);
                b1 = fma2(q.y, Mhi[2 * k + 1], b1);
            }
            float x0, x1, y0, y1;
            unpack2(add2(a0, a1), x0, x1);
            unpack2(add2(b0, b1), y0, y1);

            const float pn_lo = (x0 + x1) * er_lo;
            const float pn_hi = (y0 + y1) * er_hi;

            // branch-free freeze (uniform predicate)
            const bool upd = (t < len);
            p_lo = upd ? pn_lo : p_lo;
            p_hi = upd ? (vhi ? pn_hi : 0.0f) : p_hi;
            // Kahan accumulation of log-offset (off-chain)
            const float add = upd ? lp0 : 0.0f;
            const float y   = add - Ccomp;
            const float tt  = Csum + y;
            Ccomp = (tt - Csum) - y;
            Csum  = tt;
        }
    }

    // ---- log_z = C + log( sum_i p_i * exp(End_i) ) ----
    {
        float v = p_lo * __expf(Ev[lane]);
        if (vhi) v += p_hi * __expf(Ev[lane + 32]);
        #pragma unroll
        for (int o = 16; o; o >>= 1) v += __shfl_xor_sync(FULL, v, o);
        if (lane == 0) {
            const float log_z = (Csum - Ccomp) + __logf(v);
            atomicAdd(out, (log_z - seq) * (1.0f / (float)Bn));
        }
    }
}

extern "C" void kernel_launch(void* const* d_in, const int* in_sizes, int n_in,
                              void* d_out, int out_size) {
    const float* E    = (const float*)d_in[0];
    const int*   tags = (const int*)d_in[1];
    const void*  mask = (const void*)d_in[2];
    const float* Tr   = (const float*)d_in[3];
    const float* Sv   = (const float*)d_in[4];
    const float* Ev   = (const float*)d_in[5];
    float* out = (float*)d_out;

    _CRF_zero_kernel<<<1, 32>>>(out);
    _CRF_15530601742419_kernel<<<Bn / 4, 128>>>(E, tags, mask, Tr, Sv, Ev, out);
}